// round 1
// baseline (speedup 1.0000x reference)
#include <cuda_runtime.h>
#include <cuda_bf16.h>
#include <math.h>

// Problem constants
#define BB 2
#define LL 1024
#define DM 1024
#define DI 2048
#define DS 16
#define DC 4
#define NTOK (BB*LL)       // 2048
#define NBC 33             // 1 + 2*16

// ---------------- scratch (device globals; no allocation allowed) ----------
__device__ float g_xn[NTOK * DM];        // 8 MB
__device__ float g_xz[NTOK * 2 * DI];    // 32 MB  (x_i cols [0,2048), z cols [2048,4096))
__device__ float g_xc[NTOK * DI];        // 16 MB
__device__ float g_bcdt[NTOK * NBC];     // ~270 KB
__device__ float g_y[NTOK * DI];         // 16 MB

// ---------------- LayerNorm ------------------------------------------------
__global__ void ln_kernel(const float* __restrict__ x,
                          const float* __restrict__ g,
                          const float* __restrict__ b,
                          float* __restrict__ xn) {
    int tok = blockIdx.x;
    const float* xp = x + tok * DM;
    float s = 0.f, s2 = 0.f;
    for (int i = threadIdx.x; i < DM; i += 256) {
        float v = xp[i];
        s += v; s2 += v * v;
    }
    // warp reduce
    for (int off = 16; off > 0; off >>= 1) {
        s  += __shfl_xor_sync(0xffffffffu, s,  off);
        s2 += __shfl_xor_sync(0xffffffffu, s2, off);
    }
    __shared__ float shs[8], shs2[8];
    int wid = threadIdx.x >> 5, lid = threadIdx.x & 31;
    if (lid == 0) { shs[wid] = s; shs2[wid] = s2; }
    __syncthreads();
    if (wid == 0) {
        float a = (lid < 8) ? shs[lid]  : 0.f;
        float c = (lid < 8) ? shs2[lid] : 0.f;
        for (int off = 4; off > 0; off >>= 1) {
            a += __shfl_xor_sync(0xffffffffu, a, off);
            c += __shfl_xor_sync(0xffffffffu, c, off);
        }
        if (lid == 0) { shs[0] = a; shs2[0] = c; }
    }
    __syncthreads();
    float mean = shs[0] * (1.f / DM);
    float var  = shs2[0] * (1.f / DM) - mean * mean;
    float rs = rsqrtf(var + 1e-5f);
    float* op = xn + tok * DM;
    for (int i = threadIdx.x; i < DM; i += 256) {
        op[i] = (xp[i] - mean) * rs * g[i] + b[i];
    }
}

// ---------------- SGEMM 128x128x8, 256 threads, 8x8/thread -----------------
// C[M,N] = A[M,K] * B[K,N]  (+ Add[M,N] if Add != nullptr)
__global__ void __launch_bounds__(256, 2)
sgemm_kernel(const float* __restrict__ A, const float* __restrict__ B,
             const float* __restrict__ Add, float* __restrict__ C,
             int M, int N, int K) {
    __shared__ float As[8][132];   // padded: conflict-free transposed stores
    __shared__ float Bs[8][128];

    int tid = threadIdx.x;
    int bm = blockIdx.y, bn = blockIdx.x;

    int arow = tid >> 1;           // 0..127
    int acol = (tid & 1) * 4;      // 0 or 4
    int brow = tid >> 5;           // 0..7
    int bcol = (tid & 31) * 4;     // 0..124

    const float* Ap = A + (size_t)(bm * 128 + arow) * K + acol;
    const float* Bp = B + (size_t)brow * N + bn * 128 + bcol;

    int tx = tid & 15, ty = tid >> 4;
    int row0 = ty * 8, col0 = tx * 8;

    float acc[8][8];
#pragma unroll
    for (int i = 0; i < 8; i++)
#pragma unroll
        for (int j = 0; j < 8; j++) acc[i][j] = 0.f;

    for (int k0 = 0; k0 < K; k0 += 8) {
        float4 av = *(const float4*)Ap;  Ap += 8;
        float4 bv = *(const float4*)Bp;  Bp += (size_t)8 * N;

        __syncthreads();
        As[acol + 0][arow] = av.x;
        As[acol + 1][arow] = av.y;
        As[acol + 2][arow] = av.z;
        As[acol + 3][arow] = av.w;
        *(float4*)&Bs[brow][bcol] = bv;
        __syncthreads();

#pragma unroll
        for (int k = 0; k < 8; k++) {
            float a[8], b[8];
            *(float4*)(a)     = *(const float4*)&As[k][row0];
            *(float4*)(a + 4) = *(const float4*)&As[k][row0 + 4];
            *(float4*)(b)     = *(const float4*)&Bs[k][col0];
            *(float4*)(b + 4) = *(const float4*)&Bs[k][col0 + 4];
#pragma unroll
            for (int i = 0; i < 8; i++)
#pragma unroll
                for (int j = 0; j < 8; j++)
                    acc[i][j] = fmaf(a[i], b[j], acc[i][j]);
        }
    }

#pragma unroll
    for (int i = 0; i < 8; i++) {
        int row = bm * 128 + row0 + i;
        size_t base = (size_t)row * N + bn * 128 + col0;
        if (Add) {
#pragma unroll
            for (int j = 0; j < 8; j++) acc[i][j] += Add[base + j];
        }
        *(float4*)&C[base]     = *(float4*)&acc[i][0];
        *(float4*)&C[base + 4] = *(float4*)&acc[i][4];
    }
}

// ---------------- depthwise causal conv + SiLU -----------------------------
__global__ void conv_kernel(const float* __restrict__ xz,
                            const float* __restrict__ cw,
                            const float* __restrict__ cb,
                            float* __restrict__ xc) {
    int idx = blockIdx.x * blockDim.x + threadIdx.x;   // NTOK*DI
    int d = idx & (DI - 1);
    int tok = idx >> 11;
    int l = tok & (LL - 1);
    float acc = cb[d];
#pragma unroll
    for (int k = 0; k < DC; k++) {
        int t = l - (DC - 1) + k;
        if (t >= 0)
            acc += xz[(size_t)(tok - (DC - 1) + k) * (2 * DI) + d] * cw[d * DC + k];
    }
    float sig = 1.f / (1.f + __expf(-acc));
    xc[idx] = acc * sig;
}

// ---------------- bcdt = xc @ W_x  (K=2048, N=33) --------------------------
// 16 tokens per block (256 thr), 16 lanes per token, smem-staged W_x chunks.
__global__ void __launch_bounds__(256)
bcdt_kernel(const float* __restrict__ xc, const float* __restrict__ Wx,
            float* __restrict__ bcdt) {
    __shared__ float Ws[256 * NBC];   // 33.8 KB
    int tid = threadIdx.x;
    int tok = blockIdx.x * 16 + (tid >> 4);
    int s = tid & 15;

    float acc[NBC];
#pragma unroll
    for (int j = 0; j < NBC; j++) acc[j] = 0.f;

    const float* xrow = xc + (size_t)tok * DI;

    for (int k0 = 0; k0 < DI; k0 += 256) {
        __syncthreads();
        for (int i = tid; i < 256 * NBC; i += 256)
            Ws[i] = Wx[(size_t)k0 * NBC + i];
        __syncthreads();
        for (int kk = s; kk < 256; kk += 16) {
            float xv = xrow[k0 + kk];
            int base = kk * NBC;
#pragma unroll
            for (int j = 0; j < NBC; j++)
                acc[j] = fmaf(xv, Ws[base + j], acc[j]);
        }
    }
    // reduce over 16 lanes (xor stays within 16-lane group)
#pragma unroll
    for (int j = 0; j < NBC; j++) {
        acc[j] += __shfl_xor_sync(0xffffffffu, acc[j], 1);
        acc[j] += __shfl_xor_sync(0xffffffffu, acc[j], 2);
        acc[j] += __shfl_xor_sync(0xffffffffu, acc[j], 4);
        acc[j] += __shfl_xor_sync(0xffffffffu, acc[j], 8);
    }
    float* orow = bcdt + (size_t)tok * NBC;
    orow[s]      = acc[s];
    orow[16 + s] = acc[16 + s];
    if (s == 0) orow[32] = acc[32];
}

// ---------------- SSM scan + gating ----------------------------------------
// warp = (batch, channel pair); lane = (which channel)<<4 | state
__global__ void __launch_bounds__(256)
scan_kernel(const float* __restrict__ bcdt, const float* __restrict__ xc,
            const float* __restrict__ xz,
            const float* __restrict__ w_dt, const float* __restrict__ b_dt,
            const float* __restrict__ A_log, const float* __restrict__ Dp,
            float* __restrict__ y) {
    int gwarp = (blockIdx.x * blockDim.x + threadIdx.x) >> 5;
    int lane = threadIdx.x & 31;
    int b = gwarp >> 10;                 // DI/2 = 1024 warps per batch
    int pair = gwarp & 1023;
    int c = pair * 2 + (lane >> 4);
    int s = lane & 15;

    float Aval = -expf(A_log[c * DS + s]);
    float wdt = w_dt[c], bdt = b_dt[c], Dv = Dp[c];
    float h = 0.f;

    const float* brow = bcdt + (size_t)b * LL * NBC;
    size_t base = (size_t)b * LL;

    for (int t = 0; t < LL; t++) {
        const float* r = brow + t * NBC;
        float dtraw = r[0];
        float Bv = r[1 + s];
        float Cv = r[17 + s];
        float xcv = xc[(base + t) * DI + c];

        float u = fmaf(dtraw, wdt, bdt);
        float dt = (u > 20.f) ? u : log1pf(__expf(u));
        float dA = __expf(dt * Aval);
        h = fmaf(dA, h, dt * Bv * xcv);

        float p = h * Cv;
        p += __shfl_xor_sync(0xffffffffu, p, 1);
        p += __shfl_xor_sync(0xffffffffu, p, 2);
        p += __shfl_xor_sync(0xffffffffu, p, 4);
        p += __shfl_xor_sync(0xffffffffu, p, 8);

        if (s == 0) {
            float zv = xz[(base + t) * (2 * DI) + DI + c];
            float sig = 1.f / (1.f + __expf(-zv));
            y[(base + t) * DI + c] = (p + xcv * Dv) * (zv * sig);
        }
    }
}

// ---------------- launch ---------------------------------------------------
extern "C" void kernel_launch(void* const* d_in, const int* in_sizes, int n_in,
                              void* d_out, int out_size) {
    const float* x      = (const float*)d_in[0];
    const float* ln_g   = (const float*)d_in[1];
    const float* ln_b   = (const float*)d_in[2];
    const float* W_in   = (const float*)d_in[3];
    const float* conv_w = (const float*)d_in[4];
    const float* conv_b = (const float*)d_in[5];
    const float* W_x    = (const float*)d_in[6];
    const float* w_dt   = (const float*)d_in[7];
    const float* b_dt   = (const float*)d_in[8];
    const float* A_log  = (const float*)d_in[9];
    const float* D_par  = (const float*)d_in[10];
    const float* W_out  = (const float*)d_in[11];
    float* out = (float*)d_out;

    float *xn, *xz, *xc, *bcdt, *y;
    cudaGetSymbolAddress((void**)&xn,   g_xn);
    cudaGetSymbolAddress((void**)&xz,   g_xz);
    cudaGetSymbolAddress((void**)&xc,   g_xc);
    cudaGetSymbolAddress((void**)&bcdt, g_bcdt);
    cudaGetSymbolAddress((void**)&y,    g_y);

    // 1. LayerNorm
    ln_kernel<<<NTOK, 256>>>(x, ln_g, ln_b, xn);

    // 2. xz = xn @ W_in   [2048,1024]x[1024,4096]
    {
        dim3 grid(2 * DI / 128, NTOK / 128);
        sgemm_kernel<<<grid, 256>>>(xn, W_in, nullptr, xz, NTOK, 2 * DI, DM);
    }

    // 3. depthwise conv + SiLU
    conv_kernel<<<(NTOK * DI) / 256, 256>>>(xz, conv_w, conv_b, xc);

    // 4. bcdt = xc @ W_x
    bcdt_kernel<<<NTOK / 16, 256>>>(xc, W_x, bcdt);

    // 5. scan + gating
    scan_kernel<<<(BB * DI / 2) * 32 / 256, 256>>>(bcdt, xc, xz, w_dt, b_dt,
                                                   A_log, D_par, y);

    // 6. out = y @ W_out + x   [2048,2048]x[2048,1024]
    {
        dim3 grid(DM / 128, NTOK / 128);
        sgemm_kernel<<<grid, 256>>>(y, W_out, x, out, NTOK, DM, DI);
    }
}

// round 7
// speedup vs baseline: 1.8284x; 1.8284x over previous
#include <cuda_runtime.h>
#include <cuda_bf16.h>
#include <mma.h>
#include <math.h>
#include <stdint.h>

using namespace nvcuda;

// Problem constants
#define BB 2
#define LL 1024
#define DM 1024
#define DI 2048
#define DS 16
#define DC 4
#define NTOK (BB*LL)       // 2048
#define NBC 33             // 1 + 2*16

// ---------------- scratch (device globals; no allocation allowed) ----------
__device__ __nv_bfloat16 g_xnb[NTOK * DM];         // 4 MB  (LN output, bf16)
__device__ float         g_xz[NTOK * 2 * DI];      // 32 MB (x_i [0,2048), z [2048,4096))
__device__ float         g_xc[NTOK * DI];          // 16 MB
__device__ float         g_bcdt[NTOK * NBC];       // ~270 KB
__device__ __nv_bfloat16 g_yb[NTOK * DI];          // 8 MB  (scan output, bf16)
__device__ __nv_bfloat16 g_WinT[(2*DI) * DM];      // 8 MB  (W_in^T bf16, [N][K])
__device__ __nv_bfloat16 g_WoutT[DM * DI];         // 4 MB  (W_out^T bf16, [N][K])

// ---------------- LayerNorm -> bf16 ----------------------------------------
__global__ void ln_kernel(const float* __restrict__ x,
                          const float* __restrict__ g,
                          const float* __restrict__ b,
                          __nv_bfloat16* __restrict__ xn) {
    int tok = blockIdx.x;
    const float* xp = x + tok * DM;
    float s = 0.f, s2 = 0.f;
    for (int i = threadIdx.x; i < DM; i += 256) {
        float v = xp[i];
        s += v; s2 += v * v;
    }
    for (int off = 16; off > 0; off >>= 1) {
        s  += __shfl_xor_sync(0xffffffffu, s,  off);
        s2 += __shfl_xor_sync(0xffffffffu, s2, off);
    }
    __shared__ float shs[8], shs2[8];
    int wid = threadIdx.x >> 5, lid = threadIdx.x & 31;
    if (lid == 0) { shs[wid] = s; shs2[wid] = s2; }
    __syncthreads();
    if (wid == 0) {
        float a = (lid < 8) ? shs[lid]  : 0.f;
        float c = (lid < 8) ? shs2[lid] : 0.f;
        for (int off = 4; off > 0; off >>= 1) {
            a += __shfl_xor_sync(0xffffffffu, a, off);
            c += __shfl_xor_sync(0xffffffffu, c, off);
        }
        if (lid == 0) { shs[0] = a; shs2[0] = c; }
    }
    __syncthreads();
    float mean = shs[0] * (1.f / DM);
    float var  = shs2[0] * (1.f / DM) - mean * mean;
    float rs = rsqrtf(var + 1e-5f);
    __nv_bfloat16* op = xn + tok * DM;
    for (int i = threadIdx.x; i < DM; i += 256) {
        op[i] = __float2bfloat16((xp[i] - mean) * rs * g[i] + b[i]);
    }
}

// ---------------- transpose + convert W[K][N] fp32 -> WT[N][K] bf16 --------
__global__ void transpose_bf16(const float* __restrict__ W,
                               __nv_bfloat16* __restrict__ WT, int K, int N) {
    __shared__ float t[32][33];
    int kx = blockIdx.y * 32, nx = blockIdx.x * 32;
    int tx = threadIdx.x, ty = threadIdx.y;   // 32 x 8
#pragma unroll
    for (int i = 0; i < 32; i += 8)
        t[ty + i][tx] = W[(size_t)(kx + ty + i) * N + nx + tx];
    __syncthreads();
#pragma unroll
    for (int i = 0; i < 32; i += 8)
        WT[(size_t)(nx + ty + i) * K + kx + tx] = __float2bfloat16(t[tx][ty + i]);
}

// ---------------- WMMA bf16 GEMM -------------------------------------------
// C[M,N] (fp32) = A[M,K](bf16 row-major) @ Bt[N,K](bf16 row-major)^T (+Add)
// CTA tile 128x128, 8 warps (2x4), warp tile 64x32, K chunk 32.
#define LDM 40   // smem leading dim (bf16 elems): conflict-free LDSM
template<bool ADDRES>
__global__ void __launch_bounds__(256)
gemm_wmma(const __nv_bfloat16* __restrict__ A,
          const __nv_bfloat16* __restrict__ Bt,
          const float* __restrict__ Add,
          float* __restrict__ C, int M, int N, int K) {
    __shared__ __nv_bfloat16 As[128 * LDM];
    __shared__ __nv_bfloat16 Bs[128 * LDM];

    int tid = threadIdx.x;
    int wid = tid >> 5;
    int warp_m = wid & 1;      // 0..1  -> 64-row slab
    int warp_n = wid >> 1;     // 0..3  -> 32-col slab
    int bm = blockIdx.y, bn = blockIdx.x;

    wmma::fragment<wmma::accumulator, 16, 16, 16, float> acc[4][2];
#pragma unroll
    for (int i = 0; i < 4; i++)
#pragma unroll
        for (int j = 0; j < 2; j++) wmma::fill_fragment(acc[i][j], 0.f);

    const __nv_bfloat16* Ap = A  + (size_t)bm * 128 * K;
    const __nv_bfloat16* Bp = Bt + (size_t)bn * 128 * K;

    for (int k0 = 0; k0 < K; k0 += 32) {
#pragma unroll
        for (int it = 0; it < 2; it++) {
            int i = tid + it * 256;        // 0..511
            int row = i >> 2, seg = i & 3; // 128 rows x 4 segs of 8 bf16
            uint4 va = *(const uint4*)(Ap + (size_t)row * K + k0 + seg * 8);
            *(uint4*)(As + row * LDM + seg * 8) = va;
            uint4 vb = *(const uint4*)(Bp + (size_t)row * K + k0 + seg * 8);
            *(uint4*)(Bs + row * LDM + seg * 8) = vb;
        }
        __syncthreads();

#pragma unroll
        for (int ks = 0; ks < 2; ks++) {
            wmma::fragment<wmma::matrix_a, 16, 16, 16, __nv_bfloat16, wmma::row_major> af[4];
            wmma::fragment<wmma::matrix_b, 16, 16, 16, __nv_bfloat16, wmma::col_major> bf[2];
#pragma unroll
            for (int i = 0; i < 4; i++)
                wmma::load_matrix_sync(af[i], As + (warp_m * 64 + i * 16) * LDM + ks * 16, LDM);
#pragma unroll
            for (int j = 0; j < 2; j++)
                wmma::load_matrix_sync(bf[j], Bs + (warp_n * 32 + j * 16) * LDM + ks * 16, LDM);
#pragma unroll
            for (int i = 0; i < 4; i++)
#pragma unroll
                for (int j = 0; j < 2; j++)
                    wmma::mma_sync(acc[i][j], af[i], bf[j], acc[i][j]);
        }
        __syncthreads();
    }

    // epilogue
#pragma unroll
    for (int i = 0; i < 4; i++) {
#pragma unroll
        for (int j = 0; j < 2; j++) {
            int row = bm * 128 + warp_m * 64 + i * 16;
            int col = bn * 128 + warp_n * 32 + j * 16;
            float* cp = C + (size_t)row * N + col;
            if (ADDRES) {
                wmma::fragment<wmma::accumulator, 16, 16, 16, float> ad;
                wmma::load_matrix_sync(ad, Add + (size_t)row * N + col, N,
                                       wmma::mem_row_major);
#pragma unroll
                for (int e = 0; e < ad.num_elements; e++)
                    acc[i][j].x[e] += ad.x[e];
            }
            wmma::store_matrix_sync(cp, acc[i][j], N, wmma::mem_row_major);
        }
    }
}

// ---------------- depthwise causal conv + SiLU -----------------------------
__global__ void conv_kernel(const float* __restrict__ xz,
                            const float* __restrict__ cw,
                            const float* __restrict__ cb,
                            float* __restrict__ xc) {
    int idx = blockIdx.x * blockDim.x + threadIdx.x;   // NTOK*DI
    int d = idx & (DI - 1);
    int tok = idx >> 11;
    int l = tok & (LL - 1);
    float acc = cb[d];
#pragma unroll
    for (int k = 0; k < DC; k++) {
        int t = l - (DC - 1) + k;
        if (t >= 0)
            acc += xz[(size_t)(tok - (DC - 1) + k) * (2 * DI) + d] * cw[d * DC + k];
    }
    float sig = 1.f / (1.f + __expf(-acc));
    xc[idx] = acc * sig;
}

// ---------------- bcdt = xc @ W_x  (K=2048, N=33) --------------------------
// 8 tokens per block (256 thr), 32 lanes per token, smem-staged W_x chunks.
__global__ void __launch_bounds__(256)
bcdt_kernel(const float* __restrict__ xc, const float* __restrict__ Wx,
            float* __restrict__ bcdt) {
    __shared__ float Ws[256 * NBC];   // 33.8 KB
    int tid = threadIdx.x;
    int tok = blockIdx.x * 8 + (tid >> 5);
    int s = tid & 31;

    float acc[NBC];
#pragma unroll
    for (int j = 0; j < NBC; j++) acc[j] = 0.f;

    const float* xrow = xc + (size_t)tok * DI;

    for (int k0 = 0; k0 < DI; k0 += 256) {
        __syncthreads();
        for (int i = tid; i < 256 * NBC; i += 256)
            Ws[i] = Wx[(size_t)k0 * NBC + i];
        __syncthreads();
#pragma unroll
        for (int kk = s; kk < 256; kk += 32) {
            float xv = xrow[k0 + kk];
            int base = kk * NBC;
#pragma unroll
            for (int j = 0; j < NBC; j++)
                acc[j] = fmaf(xv, Ws[base + j], acc[j]);
        }
    }
#pragma unroll
    for (int j = 0; j < NBC; j++) {
        acc[j] += __shfl_xor_sync(0xffffffffu, acc[j], 1);
        acc[j] += __shfl_xor_sync(0xffffffffu, acc[j], 2);
        acc[j] += __shfl_xor_sync(0xffffffffu, acc[j], 4);
        acc[j] += __shfl_xor_sync(0xffffffffu, acc[j], 8);
        acc[j] += __shfl_xor_sync(0xffffffffu, acc[j], 16);
    }
    float* orow = bcdt + (size_t)tok * NBC;
    orow[s] = acc[s];
    if (s == 0) orow[32] = acc[32];
}

// ---------------- SSM scan + gating -> bf16 y ------------------------------
__global__ void __launch_bounds__(256)
scan_kernel(const float* __restrict__ bcdt, const float* __restrict__ xc,
            const float* __restrict__ xz,
            const float* __restrict__ w_dt, const float* __restrict__ b_dt,
            const float* __restrict__ A_log, const float* __restrict__ Dp,
            __nv_bfloat16* __restrict__ y) {
    int gwarp = (blockIdx.x * blockDim.x + threadIdx.x) >> 5;
    int lane = threadIdx.x & 31;
    int b = gwarp >> 10;
    int pair = gwarp & 1023;
    int c = pair * 2 + (lane >> 4);
    int s = lane & 15;

    float Aval = -expf(A_log[c * DS + s]);
    float wdt = w_dt[c], bdt = b_dt[c], Dv = Dp[c];
    float h = 0.f;

    const float* brow = bcdt + (size_t)b * LL * NBC;
    size_t base = (size_t)b * LL;

    for (int t = 0; t < LL; t++) {
        const float* r = brow + t * NBC;
        float dtraw = r[0];
        float Bv = r[1 + s];
        float Cv = r[17 + s];
        float xcv = xc[(base + t) * DI + c];

        float u = fmaf(dtraw, wdt, bdt);
        float dt = (u > 20.f) ? u : log1pf(__expf(u));
        float dA = __expf(dt * Aval);
        h = fmaf(dA, h, dt * Bv * xcv);

        float p = h * Cv;
        p += __shfl_xor_sync(0xffffffffu, p, 1);
        p += __shfl_xor_sync(0xffffffffu, p, 2);
        p += __shfl_xor_sync(0xffffffffu, p, 4);
        p += __shfl_xor_sync(0xffffffffu, p, 8);

        if (s == 0) {
            float zv = xz[(base + t) * (2 * DI) + DI + c];
            float sig = 1.f / (1.f + __expf(-zv));
            y[(base + t) * DI + c] = __float2bfloat16((p + xcv * Dv) * (zv * sig));
        }
    }
}

// ---------------- launch ---------------------------------------------------
extern "C" void kernel_launch(void* const* d_in, const int* in_sizes, int n_in,
                              void* d_out, int out_size) {
    const float* x      = (const float*)d_in[0];
    const float* ln_g   = (const float*)d_in[1];
    const float* ln_b   = (const float*)d_in[2];
    const float* W_in   = (const float*)d_in[3];
    const float* conv_w = (const float*)d_in[4];
    const float* conv_b = (const float*)d_in[5];
    const float* W_x    = (const float*)d_in[6];
    const float* w_dt   = (const float*)d_in[7];
    const float* b_dt   = (const float*)d_in[8];
    const float* A_log  = (const float*)d_in[9];
    const float* D_par  = (const float*)d_in[10];
    const float* W_out  = (const float*)d_in[11];
    float* out = (float*)d_out;

    __nv_bfloat16 *xnb, *yb, *WinT, *WoutT;
    float *xz, *xc, *bcdt;
    cudaGetSymbolAddress((void**)&xnb,   g_xnb);
    cudaGetSymbolAddress((void**)&xz,    g_xz);
    cudaGetSymbolAddress((void**)&xc,    g_xc);
    cudaGetSymbolAddress((void**)&bcdt,  g_bcdt);
    cudaGetSymbolAddress((void**)&yb,    g_yb);
    cudaGetSymbolAddress((void**)&WinT,  g_WinT);
    cudaGetSymbolAddress((void**)&WoutT, g_WoutT);

    // 1. LayerNorm -> bf16
    ln_kernel<<<NTOK, 256>>>(x, ln_g, ln_b, xnb);

    // 2a. W_in^T bf16  [1024,4096] -> [4096,1024]
    transpose_bf16<<<dim3(2 * DI / 32, DM / 32), dim3(32, 8)>>>(W_in, WinT, DM, 2 * DI);

    // 2b. xz = xn @ W_in  [2048,1024]x[1024,4096]
    gemm_wmma<false><<<dim3(2 * DI / 128, NTOK / 128), 256>>>(
        xnb, WinT, nullptr, xz, NTOK, 2 * DI, DM);

    // 3. depthwise conv + SiLU
    conv_kernel<<<(NTOK * DI) / 256, 256>>>(xz, conv_w, conv_b, xc);

    // 4. bcdt = xc @ W_x
    bcdt_kernel<<<NTOK / 8, 256>>>(xc, W_x, bcdt);

    // 5. scan + gating -> bf16 y
    scan_kernel<<<(BB * DI / 2) * 32 / 256, 256>>>(bcdt, xc, xz, w_dt, b_dt,
                                                   A_log, D_par, yb);

    // 6a. W_out^T bf16  [2048,1024] -> [1024,2048]
    transpose_bf16<<<dim3(DM / 32, DI / 32), dim3(32, 8)>>>(W_out, WoutT, DI, DM);

    // 6b. out = y @ W_out + x  [2048,2048]x[2048,1024]
    gemm_wmma<true><<<dim3(DM / 128, NTOK / 128), 256>>>(
        yb, WoutT, x, out, NTOK, DM, DI);
}

// round 8
// speedup vs baseline: 4.5877x; 2.5091x over previous
#include <cuda_runtime.h>
#include <cuda_bf16.h>
#include <mma.h>
#include <math.h>
#include <stdint.h>

using namespace nvcuda;

// Problem constants
#define BB 2
#define LL 1024
#define DM 1024
#define DI 2048
#define DS 16
#define DC 4
#define NTOK (BB*LL)       // 2048
#define NBC 33             // 1 + 2*16

// ---------------- scratch (device globals; no allocation allowed) ----------
__device__ __nv_bfloat16 g_xnb[NTOK * DM];         // 4 MB  (LN output, bf16)
__device__ float         g_xz[NTOK * 2 * DI];      // 32 MB (x_i [0,2048), z [2048,4096))
__device__ float         g_xc[NTOK * DI];          // 16 MB
__device__ float         g_gate[NTOK * DI];        // 16 MB (silu(z))
__device__ float         g_bcdt[NTOK * NBC];       // ~270 KB
__device__ __nv_bfloat16 g_yb[NTOK * DI];          // 8 MB  (scan output, bf16)
__device__ __nv_bfloat16 g_WinT[(2*DI) * DM];      // 8 MB  (W_in^T bf16, [N][K])
__device__ __nv_bfloat16 g_WoutT[DM * DI];         // 4 MB  (W_out^T bf16, [N][K])

// ---------------- cp.async helpers -----------------------------------------
__device__ __forceinline__ void cp16(uint32_t saddr, const void* gptr) {
    asm volatile("cp.async.cg.shared.global [%0], [%1], 16;"
                 :: "r"(saddr), "l"(gptr));
}
#define CP_COMMIT() asm volatile("cp.async.commit_group;")
#define CP_WAIT(n)  asm volatile("cp.async.wait_group %0;" :: "n"(n))

// ---------------- LayerNorm -> bf16 ----------------------------------------
__global__ void ln_kernel(const float* __restrict__ x,
                          const float* __restrict__ g,
                          const float* __restrict__ b,
                          __nv_bfloat16* __restrict__ xn) {
    int tok = blockIdx.x;
    const float* xp = x + tok * DM;
    float s = 0.f, s2 = 0.f;
    for (int i = threadIdx.x; i < DM; i += 256) {
        float v = xp[i];
        s += v; s2 += v * v;
    }
    for (int off = 16; off > 0; off >>= 1) {
        s  += __shfl_xor_sync(0xffffffffu, s,  off);
        s2 += __shfl_xor_sync(0xffffffffu, s2, off);
    }
    __shared__ float shs[8], shs2[8];
    int wid = threadIdx.x >> 5, lid = threadIdx.x & 31;
    if (lid == 0) { shs[wid] = s; shs2[wid] = s2; }
    __syncthreads();
    if (wid == 0) {
        float a = (lid < 8) ? shs[lid]  : 0.f;
        float c = (lid < 8) ? shs2[lid] : 0.f;
        for (int off = 4; off > 0; off >>= 1) {
            a += __shfl_xor_sync(0xffffffffu, a, off);
            c += __shfl_xor_sync(0xffffffffu, c, off);
        }
        if (lid == 0) { shs[0] = a; shs2[0] = c; }
    }
    __syncthreads();
    float mean = shs[0] * (1.f / DM);
    float var  = shs2[0] * (1.f / DM) - mean * mean;
    float rs = rsqrtf(var + 1e-5f);
    __nv_bfloat16* op = xn + tok * DM;
    for (int i = threadIdx.x; i < DM; i += 256) {
        op[i] = __float2bfloat16((xp[i] - mean) * rs * g[i] + b[i]);
    }
}

// ---------------- transpose + convert W[K][N] fp32 -> WT[N][K] bf16 --------
__global__ void transpose_bf16(const float* __restrict__ W,
                               __nv_bfloat16* __restrict__ WT, int K, int N) {
    __shared__ float t[32][33];
    int kx = blockIdx.y * 32, nx = blockIdx.x * 32;
    int tx = threadIdx.x, ty = threadIdx.y;   // 32 x 8
#pragma unroll
    for (int i = 0; i < 32; i += 8)
        t[ty + i][tx] = W[(size_t)(kx + ty + i) * N + nx + tx];
    __syncthreads();
#pragma unroll
    for (int i = 0; i < 32; i += 8)
        WT[(size_t)(nx + ty + i) * K + kx + tx] = __float2bfloat16(t[tx][ty + i]);
}

// ---------------- WMMA bf16 GEMM with cp.async double buffering ------------
// C[M,N] (fp32) = A[M,K](bf16 row-major) @ Bt[N,K](bf16 row-major)^T (+Add)
// CTA tile 128x128, 8 warps (2x4), warp tile 64x32, K chunk 32, 2 stages.
#define LDM 40   // smem leading dim (bf16): 80B rows, 16B-aligned, conflict-free
template<bool ADDRES>
__global__ void __launch_bounds__(256)
gemm_wmma(const __nv_bfloat16* __restrict__ A,
          const __nv_bfloat16* __restrict__ Bt,
          const float* __restrict__ Add,
          float* __restrict__ C, int M, int N, int K) {
    __shared__ __nv_bfloat16 As[2][128 * LDM];
    __shared__ __nv_bfloat16 Bs[2][128 * LDM];

    int tid = threadIdx.x;
    int wid = tid >> 5;
    int warp_m = wid & 1;      // 0..1  -> 64-row slab
    int warp_n = wid >> 1;     // 0..3  -> 32-col slab
    int bm = blockIdx.y, bn = blockIdx.x;

    wmma::fragment<wmma::accumulator, 16, 16, 16, float> acc[4][2];
#pragma unroll
    for (int i = 0; i < 4; i++)
#pragma unroll
        for (int j = 0; j < 2; j++) wmma::fill_fragment(acc[i][j], 0.f);

    const __nv_bfloat16* Ap = A  + (size_t)bm * 128 * K;
    const __nv_bfloat16* Bp = Bt + (size_t)bn * 128 * K;

    // per-thread load coords: 2 x (row, seg) covering 128 rows x 4 segs
    int r0 = tid >> 2,           s0 = (tid & 3);
    int r1 = (tid + 256) >> 2,   s1 = (tid & 3);
    uint32_t sA0 = (uint32_t)__cvta_generic_to_shared(&As[0][0]);
    uint32_t sB0 = (uint32_t)__cvta_generic_to_shared(&Bs[0][0]);
    const uint32_t STG = 128 * LDM * 2;   // bytes per stage

    auto load_stage = [&](int k0, int buf) {
        uint32_t oa0 = buf * STG + (r0 * LDM + s0 * 8) * 2;
        uint32_t oa1 = buf * STG + (r1 * LDM + s1 * 8) * 2;
        cp16(sA0 + oa0, Ap + (size_t)r0 * K + k0 + s0 * 8);
        cp16(sA0 + oa1, Ap + (size_t)r1 * K + k0 + s1 * 8);
        cp16(sB0 + oa0, Bp + (size_t)r0 * K + k0 + s0 * 8);
        cp16(sB0 + oa1, Bp + (size_t)r1 * K + k0 + s1 * 8);
    };

    int KT = K / 32;
    load_stage(0, 0);
    CP_COMMIT();

    for (int kt = 0; kt < KT; kt++) {
        int buf = kt & 1;
        if (kt + 1 < KT) {
            load_stage((kt + 1) * 32, buf ^ 1);
            CP_COMMIT();
            CP_WAIT(1);
        } else {
            CP_WAIT(0);
        }
        __syncthreads();

#pragma unroll
        for (int ks = 0; ks < 2; ks++) {
            wmma::fragment<wmma::matrix_a, 16, 16, 16, __nv_bfloat16, wmma::row_major> af[4];
            wmma::fragment<wmma::matrix_b, 16, 16, 16, __nv_bfloat16, wmma::col_major> bf[2];
#pragma unroll
            for (int i = 0; i < 4; i++)
                wmma::load_matrix_sync(af[i], &As[buf][(warp_m * 64 + i * 16) * LDM + ks * 16], LDM);
#pragma unroll
            for (int j = 0; j < 2; j++)
                wmma::load_matrix_sync(bf[j], &Bs[buf][(warp_n * 32 + j * 16) * LDM + ks * 16], LDM);
#pragma unroll
            for (int i = 0; i < 4; i++)
#pragma unroll
                for (int j = 0; j < 2; j++)
                    wmma::mma_sync(acc[i][j], af[i], bf[j], acc[i][j]);
        }
        __syncthreads();
    }

    // epilogue
#pragma unroll
    for (int i = 0; i < 4; i++) {
#pragma unroll
        for (int j = 0; j < 2; j++) {
            int row = bm * 128 + warp_m * 64 + i * 16;
            int col = bn * 128 + warp_n * 32 + j * 16;
            float* cp = C + (size_t)row * N + col;
            if (ADDRES) {
                wmma::fragment<wmma::accumulator, 16, 16, 16, float> ad;
                wmma::load_matrix_sync(ad, Add + (size_t)row * N + col, N,
                                       wmma::mem_row_major);
#pragma unroll
                for (int e = 0; e < ad.num_elements; e++)
                    acc[i][j].x[e] += ad.x[e];
            }
            wmma::store_matrix_sync(cp, acc[i][j], N, wmma::mem_row_major);
        }
    }
}

// ---------------- depthwise causal conv + SiLU, plus gate = silu(z) --------
__global__ void conv_kernel(const float* __restrict__ xz,
                            const float* __restrict__ cw,
                            const float* __restrict__ cb,
                            float* __restrict__ xc,
                            float* __restrict__ gate) {
    int idx = blockIdx.x * blockDim.x + threadIdx.x;   // NTOK*DI
    int d = idx & (DI - 1);
    int tok = idx >> 11;
    int l = tok & (LL - 1);
    float acc = cb[d];
#pragma unroll
    for (int k = 0; k < DC; k++) {
        int t = l - (DC - 1) + k;
        if (t >= 0)
            acc += xz[(size_t)(tok - (DC - 1) + k) * (2 * DI) + d] * cw[d * DC + k];
    }
    float sig = 1.f / (1.f + __expf(-acc));
    xc[idx] = acc * sig;

    float zv = xz[(size_t)tok * (2 * DI) + DI + d];
    float zs = 1.f / (1.f + __expf(-zv));
    gate[idx] = zv * zs;
}

// ---------------- bcdt = xc @ W_x  (K=2048, N=33) --------------------------
__global__ void __launch_bounds__(256)
bcdt_kernel(const float* __restrict__ xc, const float* __restrict__ Wx,
            float* __restrict__ bcdt) {
    __shared__ float Ws[256 * NBC];   // 33.8 KB
    int tid = threadIdx.x;
    int tok = blockIdx.x * 8 + (tid >> 5);
    int s = tid & 31;

    float acc[NBC];
#pragma unroll
    for (int j = 0; j < NBC; j++) acc[j] = 0.f;

    const float* xrow = xc + (size_t)tok * DI;

    for (int k0 = 0; k0 < DI; k0 += 256) {
        __syncthreads();
        for (int i = tid; i < 256 * NBC; i += 256)
            Ws[i] = Wx[(size_t)k0 * NBC + i];
        __syncthreads();
#pragma unroll
        for (int kk = s; kk < 256; kk += 32) {
            float xv = xrow[k0 + kk];
            int base = kk * NBC;
#pragma unroll
            for (int j = 0; j < NBC; j++)
                acc[j] = fmaf(xv, Ws[base + j], acc[j]);
        }
    }
#pragma unroll
    for (int j = 0; j < NBC; j++) {
        acc[j] += __shfl_xor_sync(0xffffffffu, acc[j], 1);
        acc[j] += __shfl_xor_sync(0xffffffffu, acc[j], 2);
        acc[j] += __shfl_xor_sync(0xffffffffu, acc[j], 4);
        acc[j] += __shfl_xor_sync(0xffffffffu, acc[j], 8);
        acc[j] += __shfl_xor_sync(0xffffffffu, acc[j], 16);
    }
    float* orow = bcdt + (size_t)tok * NBC;
    orow[s] = acc[s];
    if (s == 0) orow[32] = acc[32];
}

// ---------------- SSM scan + gating -> bf16 y ------------------------------
// Block = (batch, 16 contiguous channels); 8 warps, each warp 2 channels x 16
// states. All operands staged in smem per 64-step chunk.
#define TCH 64
__global__ void __launch_bounds__(256)
scan_kernel(const float* __restrict__ bcdt, const float* __restrict__ xc,
            const float* __restrict__ gate,
            const float* __restrict__ w_dt, const float* __restrict__ b_dt,
            const float* __restrict__ A_log, const float* __restrict__ Dp,
            __nv_bfloat16* __restrict__ y) {
    __shared__ float s_b[TCH][34];     // bcdt rows (33 used)
    __shared__ float s_xc[TCH][16];
    __shared__ float s_g[TCH][16];

    int tid = threadIdx.x;
    int wid = tid >> 5, lane = tid & 31;
    int blk = blockIdx.x;              // 256 blocks
    int b = blk >> 7;                  // 128 blocks per batch
    int c0 = (blk & 127) * 16;
    int ch = wid * 2 + (lane >> 4);    // 0..15 within block
    int c = c0 + ch;
    int s = lane & 15;

    float Aval = -expf(A_log[c * DS + s]);
    float wdt = w_dt[c], bdt = b_dt[c], Dv = Dp[c];
    float h = 0.f;
    size_t base = (size_t)b * LL;

    for (int t0 = 0; t0 < LL; t0 += TCH) {
        __syncthreads();
        // stage bcdt: TCH*33 contiguous floats, fully coalesced
        {
            const float* src = bcdt + (base + t0) * NBC;
            for (int i = tid; i < TCH * NBC; i += 256) {
                int tt = i / NBC, jj = i - tt * NBC;
                s_b[tt][jj] = src[i];
            }
        }
        // stage xc, gate segments: TCH x 16
        for (int i = tid; i < TCH * 16; i += 256) {
            int tt = i >> 4, cc = i & 15;
            size_t off = (base + t0 + tt) * DI + c0 + cc;
            s_xc[tt][cc] = xc[off];
            s_g[tt][cc]  = gate[off];
        }
        __syncthreads();

#pragma unroll 4
        for (int tt = 0; tt < TCH; tt++) {
            float dtraw = s_b[tt][0];
            float Bv = s_b[tt][1 + s];
            float Cv = s_b[tt][17 + s];
            float xcv = s_xc[tt][ch];

            float u = fmaf(dtraw, wdt, bdt);
            float eu = __expf(-fabsf(u));
            float dt = fmaxf(u, 0.f) + __logf(1.f + eu);
            float dA = __expf(dt * Aval);
            h = fmaf(dA, h, dt * Bv * xcv);

            float p = h * Cv;
            p += __shfl_xor_sync(0xffffffffu, p, 1);
            p += __shfl_xor_sync(0xffffffffu, p, 2);
            p += __shfl_xor_sync(0xffffffffu, p, 4);
            p += __shfl_xor_sync(0xffffffffu, p, 8);

            if (s == 0) {
                y[(base + t0 + tt) * DI + c] =
                    __float2bfloat16((p + xcv * Dv) * s_g[tt][ch]);
            }
        }
    }
}

// ---------------- launch ---------------------------------------------------
extern "C" void kernel_launch(void* const* d_in, const int* in_sizes, int n_in,
                              void* d_out, int out_size) {
    const float* x      = (const float*)d_in[0];
    const float* ln_g   = (const float*)d_in[1];
    const float* ln_b   = (const float*)d_in[2];
    const float* W_in   = (const float*)d_in[3];
    const float* conv_w = (const float*)d_in[4];
    const float* conv_b = (const float*)d_in[5];
    const float* W_x    = (const float*)d_in[6];
    const float* w_dt   = (const float*)d_in[7];
    const float* b_dt   = (const float*)d_in[8];
    const float* A_log  = (const float*)d_in[9];
    const float* D_par  = (const float*)d_in[10];
    const float* W_out  = (const float*)d_in[11];
    float* out = (float*)d_out;

    __nv_bfloat16 *xnb, *yb, *WinT, *WoutT;
    float *xz, *xc, *gate, *bcdt;
    cudaGetSymbolAddress((void**)&xnb,   g_xnb);
    cudaGetSymbolAddress((void**)&xz,    g_xz);
    cudaGetSymbolAddress((void**)&xc,    g_xc);
    cudaGetSymbolAddress((void**)&gate,  g_gate);
    cudaGetSymbolAddress((void**)&bcdt,  g_bcdt);
    cudaGetSymbolAddress((void**)&yb,    g_yb);
    cudaGetSymbolAddress((void**)&WinT,  g_WinT);
    cudaGetSymbolAddress((void**)&WoutT, g_WoutT);

    // 1. LayerNorm -> bf16
    ln_kernel<<<NTOK, 256>>>(x, ln_g, ln_b, xnb);

    // 2a. W_in^T bf16  [1024,4096] -> [4096,1024]
    transpose_bf16<<<dim3(2 * DI / 32, DM / 32), dim3(32, 8)>>>(W_in, WinT, DM, 2 * DI);

    // 2b. xz = xn @ W_in  [2048,1024]x[1024,4096]
    gemm_wmma<false><<<dim3(2 * DI / 128, NTOK / 128), 256>>>(
        xnb, WinT, nullptr, xz, NTOK, 2 * DI, DM);

    // 3. depthwise conv + SiLU + gate
    conv_kernel<<<(NTOK * DI) / 256, 256>>>(xz, conv_w, conv_b, xc, gate);

    // 4. bcdt = xc @ W_x
    bcdt_kernel<<<NTOK / 8, 256>>>(xc, W_x, bcdt);

    // 5. scan + gating -> bf16 y
    scan_kernel<<<256, 256>>>(bcdt, xc, gate, w_dt, b_dt, A_log, D_par, yb);

    // 6a. W_out^T bf16  [2048,1024] -> [1024,2048]
    transpose_bf16<<<dim3(DM / 32, DI / 32), dim3(32, 8)>>>(W_out, WoutT, DI, DM);

    // 6b. out = y @ W_out + x  [2048,2048]x[2048,1024]
    gemm_wmma<true><<<dim3(DM / 128, NTOK / 128), 256>>>(
        yb, WoutT, x, out, NTOK, DM, DI);
}

// round 9
// speedup vs baseline: 5.3262x; 1.1610x over previous
#include <cuda_runtime.h>
#include <cuda_bf16.h>
#include <mma.h>
#include <math.h>
#include <stdint.h>

using namespace nvcuda;

// Problem constants
#define BB 2
#define LL 1024
#define DM 1024
#define DI 2048
#define DS 16
#define DC 4
#define NTOK (BB*LL)       // 2048
#define NBC 33             // 1 + 2*16

// ---------------- scratch (device globals; no allocation allowed) ----------
__device__ __nv_bfloat16 g_xnb[NTOK * DM];         // 4 MB  (LN output, bf16)
__device__ float         g_xz[NTOK * 2 * DI];      // 32 MB (x_i [0,2048), z [2048,4096))
__device__ float         g_xc[NTOK * DI];          // 16 MB
__device__ float         g_gate[NTOK * DI];        // 16 MB (silu(z))
__device__ float         g_bcdt[NTOK * NBC];       // ~270 KB
__device__ __nv_bfloat16 g_yb[NTOK * DI];          // 8 MB  (scan output, bf16)
__device__ __nv_bfloat16 g_WinT[(2*DI) * DM];      // 8 MB  (W_in^T bf16, [N][K])
__device__ __nv_bfloat16 g_WoutT[DM * DI];         // 4 MB  (W_out^T bf16, [N][K])

// ---------------- cp.async helpers -----------------------------------------
__device__ __forceinline__ void cp16(uint32_t saddr, const void* gptr) {
    asm volatile("cp.async.cg.shared.global [%0], [%1], 16;"
                 :: "r"(saddr), "l"(gptr));
}
#define CP_COMMIT() asm volatile("cp.async.commit_group;")
#define CP_WAIT(n)  asm volatile("cp.async.wait_group %0;" :: "n"(n))

// ---------------- LayerNorm -> bf16 ----------------------------------------
__global__ void ln_kernel(const float* __restrict__ x,
                          const float* __restrict__ g,
                          const float* __restrict__ b,
                          __nv_bfloat16* __restrict__ xn) {
    int tok = blockIdx.x;
    const float* xp = x + tok * DM;
    float s = 0.f, s2 = 0.f;
    for (int i = threadIdx.x; i < DM; i += 256) {
        float v = xp[i];
        s += v; s2 += v * v;
    }
    for (int off = 16; off > 0; off >>= 1) {
        s  += __shfl_xor_sync(0xffffffffu, s,  off);
        s2 += __shfl_xor_sync(0xffffffffu, s2, off);
    }
    __shared__ float shs[8], shs2[8];
    int wid = threadIdx.x >> 5, lid = threadIdx.x & 31;
    if (lid == 0) { shs[wid] = s; shs2[wid] = s2; }
    __syncthreads();
    if (wid == 0) {
        float a = (lid < 8) ? shs[lid]  : 0.f;
        float c = (lid < 8) ? shs2[lid] : 0.f;
        for (int off = 4; off > 0; off >>= 1) {
            a += __shfl_xor_sync(0xffffffffu, a, off);
            c += __shfl_xor_sync(0xffffffffu, c, off);
        }
        if (lid == 0) { shs[0] = a; shs2[0] = c; }
    }
    __syncthreads();
    float mean = shs[0] * (1.f / DM);
    float var  = shs2[0] * (1.f / DM) - mean * mean;
    float rs = rsqrtf(var + 1e-5f);
    __nv_bfloat16* op = xn + tok * DM;
    for (int i = threadIdx.x; i < DM; i += 256) {
        op[i] = __float2bfloat16((xp[i] - mean) * rs * g[i] + b[i]);
    }
}

// ---------------- transpose + convert W[K][N] fp32 -> WT[N][K] bf16 --------
__global__ void transpose_bf16(const float* __restrict__ W,
                               __nv_bfloat16* __restrict__ WT, int K, int N) {
    __shared__ float t[32][33];
    int kx = blockIdx.y * 32, nx = blockIdx.x * 32;
    int tx = threadIdx.x, ty = threadIdx.y;   // 32 x 8
#pragma unroll
    for (int i = 0; i < 32; i += 8)
        t[ty + i][tx] = W[(size_t)(kx + ty + i) * N + nx + tx];
    __syncthreads();
#pragma unroll
    for (int i = 0; i < 32; i += 8)
        WT[(size_t)(nx + ty + i) * K + kx + tx] = __float2bfloat16(t[tx][ty + i]);
}

// ---------------- WMMA bf16 GEMM with cp.async double buffering ------------
// C[M,N] (fp32) = A[M,K](bf16 row-major) @ Bt[N,K](bf16 row-major)^T (+Add)
// CTA tile 128x128, 8 warps (2x4), warp tile 64x32, K chunk 32, 2 stages.
#define LDM 40   // smem leading dim (bf16): 80B rows, 16B-aligned, conflict-free
template<bool ADDRES>
__global__ void __launch_bounds__(256)
gemm_wmma(const __nv_bfloat16* __restrict__ A,
          const __nv_bfloat16* __restrict__ Bt,
          const float* __restrict__ Add,
          float* __restrict__ C, int M, int N, int K) {
    __shared__ __nv_bfloat16 As[2][128 * LDM];
    __shared__ __nv_bfloat16 Bs[2][128 * LDM];

    int tid = threadIdx.x;
    int wid = tid >> 5;
    int warp_m = wid & 1;      // 0..1  -> 64-row slab
    int warp_n = wid >> 1;     // 0..3  -> 32-col slab
    int bm = blockIdx.y, bn = blockIdx.x;

    wmma::fragment<wmma::accumulator, 16, 16, 16, float> acc[4][2];
#pragma unroll
    for (int i = 0; i < 4; i++)
#pragma unroll
        for (int j = 0; j < 2; j++) wmma::fill_fragment(acc[i][j], 0.f);

    const __nv_bfloat16* Ap = A  + (size_t)bm * 128 * K;
    const __nv_bfloat16* Bp = Bt + (size_t)bn * 128 * K;

    // per-thread load coords: 2 x (row, seg) covering 128 rows x 4 segs
    int r0 = tid >> 2,           s0 = (tid & 3);
    int r1 = (tid + 256) >> 2,   s1 = (tid & 3);
    uint32_t sA0 = (uint32_t)__cvta_generic_to_shared(&As[0][0]);
    uint32_t sB0 = (uint32_t)__cvta_generic_to_shared(&Bs[0][0]);
    const uint32_t STG = 128 * LDM * 2;   // bytes per stage

    auto load_stage = [&](int k0, int buf) {
        uint32_t oa0 = buf * STG + (r0 * LDM + s0 * 8) * 2;
        uint32_t oa1 = buf * STG + (r1 * LDM + s1 * 8) * 2;
        cp16(sA0 + oa0, Ap + (size_t)r0 * K + k0 + s0 * 8);
        cp16(sA0 + oa1, Ap + (size_t)r1 * K + k0 + s1 * 8);
        cp16(sB0 + oa0, Bp + (size_t)r0 * K + k0 + s0 * 8);
        cp16(sB0 + oa1, Bp + (size_t)r1 * K + k0 + s1 * 8);
    };

    int KT = K / 32;
    load_stage(0, 0);
    CP_COMMIT();

    for (int kt = 0; kt < KT; kt++) {
        int buf = kt & 1;
        if (kt + 1 < KT) {
            load_stage((kt + 1) * 32, buf ^ 1);
            CP_COMMIT();
            CP_WAIT(1);
        } else {
            CP_WAIT(0);
        }
        __syncthreads();

#pragma unroll
        for (int ks = 0; ks < 2; ks++) {
            wmma::fragment<wmma::matrix_a, 16, 16, 16, __nv_bfloat16, wmma::row_major> af[4];
            wmma::fragment<wmma::matrix_b, 16, 16, 16, __nv_bfloat16, wmma::col_major> bf[2];
#pragma unroll
            for (int i = 0; i < 4; i++)
                wmma::load_matrix_sync(af[i], &As[buf][(warp_m * 64 + i * 16) * LDM + ks * 16], LDM);
#pragma unroll
            for (int j = 0; j < 2; j++)
                wmma::load_matrix_sync(bf[j], &Bs[buf][(warp_n * 32 + j * 16) * LDM + ks * 16], LDM);
#pragma unroll
            for (int i = 0; i < 4; i++)
#pragma unroll
                for (int j = 0; j < 2; j++)
                    wmma::mma_sync(acc[i][j], af[i], bf[j], acc[i][j]);
        }
        __syncthreads();
    }

    // epilogue
#pragma unroll
    for (int i = 0; i < 4; i++) {
#pragma unroll
        for (int j = 0; j < 2; j++) {
            int row = bm * 128 + warp_m * 64 + i * 16;
            int col = bn * 128 + warp_n * 32 + j * 16;
            float* cp = C + (size_t)row * N + col;
            if (ADDRES) {
                wmma::fragment<wmma::accumulator, 16, 16, 16, float> ad;
                wmma::load_matrix_sync(ad, Add + (size_t)row * N + col, N,
                                       wmma::mem_row_major);
#pragma unroll
                for (int e = 0; e < ad.num_elements; e++)
                    acc[i][j].x[e] += ad.x[e];
            }
            wmma::store_matrix_sync(cp, acc[i][j], N, wmma::mem_row_major);
        }
    }
}

// ---------------- depthwise causal conv + SiLU, plus gate = silu(z) --------
__global__ void conv_kernel(const float* __restrict__ xz,
                            const float* __restrict__ cw,
                            const float* __restrict__ cb,
                            float* __restrict__ xc,
                            float* __restrict__ gate) {
    int idx = blockIdx.x * blockDim.x + threadIdx.x;   // NTOK*DI
    int d = idx & (DI - 1);
    int tok = idx >> 11;
    int l = tok & (LL - 1);
    float acc = cb[d];
#pragma unroll
    for (int k = 0; k < DC; k++) {
        int t = l - (DC - 1) + k;
        if (t >= 0)
            acc += xz[(size_t)(tok - (DC - 1) + k) * (2 * DI) + d] * cw[d * DC + k];
    }
    float sig = 1.f / (1.f + __expf(-acc));
    xc[idx] = acc * sig;

    float zv = xz[(size_t)tok * (2 * DI) + DI + d];
    float zs = 1.f / (1.f + __expf(-zv));
    gate[idx] = zv * zs;
}

// ---------------- bcdt = xc @ W_x  (K=2048, N=33) --------------------------
__global__ void __launch_bounds__(256)
bcdt_kernel(const float* __restrict__ xc, const float* __restrict__ Wx,
            float* __restrict__ bcdt) {
    __shared__ float Ws[256 * NBC];   // 33.8 KB
    int tid = threadIdx.x;
    int tok = blockIdx.x * 8 + (tid >> 5);
    int s = tid & 31;

    float acc[NBC];
#pragma unroll
    for (int j = 0; j < NBC; j++) acc[j] = 0.f;

    const float* xrow = xc + (size_t)tok * DI;

    for (int k0 = 0; k0 < DI; k0 += 256) {
        __syncthreads();
        for (int i = tid; i < 256 * NBC; i += 256)
            Ws[i] = Wx[(size_t)k0 * NBC + i];
        __syncthreads();
#pragma unroll
        for (int kk = s; kk < 256; kk += 32) {
            float xv = xrow[k0 + kk];
            int base = kk * NBC;
#pragma unroll
            for (int j = 0; j < NBC; j++)
                acc[j] = fmaf(xv, Ws[base + j], acc[j]);
        }
    }
#pragma unroll
    for (int j = 0; j < NBC; j++) {
        acc[j] += __shfl_xor_sync(0xffffffffu, acc[j], 1);
        acc[j] += __shfl_xor_sync(0xffffffffu, acc[j], 2);
        acc[j] += __shfl_xor_sync(0xffffffffu, acc[j], 4);
        acc[j] += __shfl_xor_sync(0xffffffffu, acc[j], 8);
        acc[j] += __shfl_xor_sync(0xffffffffu, acc[j], 16);
    }
    float* orow = bcdt + (size_t)tok * NBC;
    orow[s] = acc[s];
    if (s == 0) orow[32] = acc[32];
}

// ---------------- SSM scan + gating -> bf16 y ------------------------------
// Block = (batch, 32 contiguous channels), 256 thr.
// Warp = 4 channels x (8 lanes x 2 states). Softplus hoisted into staging.
#define TCH 64
__global__ void __launch_bounds__(256)
scan_kernel(const float* __restrict__ bcdt, const float* __restrict__ xc,
            const float* __restrict__ gate,
            const float* __restrict__ w_dt, const float* __restrict__ b_dt,
            const float* __restrict__ A_log, const float* __restrict__ Dp,
            __nv_bfloat16* __restrict__ y) {
    __shared__ float s_b[TCH][34];     // bcdt rows (cols 1..32 used in loop)
    __shared__ float s_dt[TCH][32];    // softplus(dt_raw*w+b)
    __shared__ float s_dxc[TCH][32];   // dt * xc
    __shared__ float s_g[TCH][32];     // silu(z)
    __shared__ float s_y0[TCH][32];    // xc * D * gate

    int tid = threadIdx.x;
    int wid = tid >> 5, lane = tid & 31;
    int blk = blockIdx.x;              // 128 blocks
    int b = blk >> 6;                  // 64 blocks per batch
    int c0 = (blk & 63) * 32;
    int ch = wid * 4 + (lane >> 3);    // 0..31 within block
    int s8 = lane & 7;                 // state pair base
    int c = c0 + ch;

    float A0 = -expf(A_log[c * DS + s8]);
    float A1 = -expf(A_log[c * DS + s8 + 8]);
    float h0 = 0.f, h1 = 0.f;
    size_t base = (size_t)b * LL;

    // per-thread staging constants (stage loops use cc = tid&31)
    int cc = tid & 31;
    float wdt = w_dt[c0 + cc], bdt = b_dt[c0 + cc], Dv = Dp[c0 + cc];

    for (int t0 = 0; t0 < LL; t0 += TCH) {
        __syncthreads();
        // stage bcdt rows: TCH*33 contiguous floats
        {
            const float* src = bcdt + (base + t0) * NBC;
            for (int i = tid; i < TCH * NBC; i += 256) {
                int tt = i / NBC, jj = i - tt * NBC;
                s_b[tt][jj] = src[i];
            }
        }
        // stage xc/gate + hoisted softplus: each thread fixed cc, 8 tt rows
#pragma unroll
        for (int k = 0; k < TCH * 32 / 256; k++) {
            int tt = (tid >> 5) + k * 8;
            size_t off = (base + t0 + tt) * DI + c0 + cc;
            float xcv = xc[off];
            float gv  = gate[off];
            float dtraw = bcdt[(base + t0 + tt) * NBC];   // L1 broadcast
            float u = fmaf(dtraw, wdt, bdt);
            float eu = __expf(-fabsf(u));
            float dt = fmaxf(u, 0.f) + __logf(1.f + eu);
            s_dt[tt][cc]  = dt;
            s_dxc[tt][cc] = dt * xcv;
            s_g[tt][cc]   = gv;
            s_y0[tt][cc]  = xcv * Dv * gv;
        }
        __syncthreads();

#pragma unroll 4
        for (int tt = 0; tt < TCH; tt++) {
            float dt  = s_dt[tt][ch];
            float dxc = s_dxc[tt][ch];
            float B0 = s_b[tt][1 + s8],  B1 = s_b[tt][9 + s8];
            float C0 = s_b[tt][17 + s8], C1 = s_b[tt][25 + s8];

            float dA0 = __expf(dt * A0);
            float dA1 = __expf(dt * A1);
            h0 = fmaf(dA0, h0, dxc * B0);
            h1 = fmaf(dA1, h1, dxc * B1);

            float p = fmaf(h1, C1, h0 * C0);
            p += __shfl_xor_sync(0xffffffffu, p, 1);
            p += __shfl_xor_sync(0xffffffffu, p, 2);
            p += __shfl_xor_sync(0xffffffffu, p, 4);

            if (s8 == 0) {
                float yv = fmaf(p, s_g[tt][ch], s_y0[tt][ch]);
                y[(base + t0 + tt) * DI + c] = __float2bfloat16(yv);
            }
        }
    }
}

// ---------------- launch ---------------------------------------------------
extern "C" void kernel_launch(void* const* d_in, const int* in_sizes, int n_in,
                              void* d_out, int out_size) {
    const float* x      = (const float*)d_in[0];
    const float* ln_g   = (const float*)d_in[1];
    const float* ln_b   = (const float*)d_in[2];
    const float* W_in   = (const float*)d_in[3];
    const float* conv_w = (const float*)d_in[4];
    const float* conv_b = (const float*)d_in[5];
    const float* W_x    = (const float*)d_in[6];
    const float* w_dt   = (const float*)d_in[7];
    const float* b_dt   = (const float*)d_in[8];
    const float* A_log  = (const float*)d_in[9];
    const float* D_par  = (const float*)d_in[10];
    const float* W_out  = (const float*)d_in[11];
    float* out = (float*)d_out;

    __nv_bfloat16 *xnb, *yb, *WinT, *WoutT;
    float *xz, *xc, *gate, *bcdt;
    cudaGetSymbolAddress((void**)&xnb,   g_xnb);
    cudaGetSymbolAddress((void**)&xz,    g_xz);
    cudaGetSymbolAddress((void**)&xc,    g_xc);
    cudaGetSymbolAddress((void**)&gate,  g_gate);
    cudaGetSymbolAddress((void**)&bcdt,  g_bcdt);
    cudaGetSymbolAddress((void**)&yb,    g_yb);
    cudaGetSymbolAddress((void**)&WinT,  g_WinT);
    cudaGetSymbolAddress((void**)&WoutT, g_WoutT);

    // 1. LayerNorm -> bf16
    ln_kernel<<<NTOK, 256>>>(x, ln_g, ln_b, xnb);

    // 2a. W_in^T bf16  [1024,4096] -> [4096,1024]
    transpose_bf16<<<dim3(2 * DI / 32, DM / 32), dim3(32, 8)>>>(W_in, WinT, DM, 2 * DI);

    // 2b. xz = xn @ W_in  [2048,1024]x[1024,4096]
    gemm_wmma<false><<<dim3(2 * DI / 128, NTOK / 128), 256>>>(
        xnb, WinT, nullptr, xz, NTOK, 2 * DI, DM);

    // 3. depthwise conv + SiLU + gate
    conv_kernel<<<(NTOK * DI) / 256, 256>>>(xz, conv_w, conv_b, xc, gate);

    // 4. bcdt = xc @ W_x
    bcdt_kernel<<<NTOK / 8, 256>>>(xc, W_x, bcdt);

    // 5. scan + gating -> bf16 y
    scan_kernel<<<128, 256>>>(bcdt, xc, gate, w_dt, b_dt, A_log, D_par, yb);

    // 6a. W_out^T bf16  [2048,1024] -> [1024,2048]
    transpose_bf16<<<dim3(DM / 32, DI / 32), dim3(32, 8)>>>(W_out, WoutT, DI, DM);

    // 6b. out = y @ W_out + x  [2048,2048]x[2048,1024]
    gemm_wmma<true><<<dim3(DM / 128, NTOK / 128), 256>>>(
        yb, WoutT, x, out, NTOK, DM, DI);
}